// round 2
// baseline (speedup 1.0000x reference)
#include <cuda_runtime.h>
#include <math.h>

#define B_  128
#define T_  96
#define V_  4096
#define TV_ (T_*V_)

// ---------------- device scratch (no runtime alloc allowed) ----------------
__device__ float g_enc[B_*512];        // sorted encoder_out
__device__ float g_att1[B_*512];       // enc @ W_enc^T + b_enc
__device__ float g_att1T[512*B_];      // transposed att1 for coalesced attn
__device__ float g_h[B_*512];
__device__ float g_c[B_*512];
__device__ float g_att2gate[B_*1024];  // [att2 | sigmoid(h@W_fbeta^T+b)]
__device__ float g_xcat[B_*1536];      // [emb | gated awe | h]
__device__ float g_gates[B_*2048];
__device__ float g_Wc1[1024*512];      // [W_dec ; W_fbeta]
__device__ float g_bc1[1024];
__device__ float g_Wbig[2048*1536];    // row r = [W_ih[r] | W_hh[r]]
__device__ float g_bbig[2048];
__device__ int   g_order[B_];
__device__ int   g_nvalid[T_];

// ---------------- prep kernels ----------------
__global__ void k_prep(const int* __restrict__ capl) {
    __shared__ int lens[B_];
    int i = threadIdx.x;
    lens[i] = capl[i];
    __syncthreads();
    int li = lens[i];
    int rank = 0;
    #pragma unroll 8
    for (int j = 0; j < B_; j++) {
        int lj = lens[j];
        rank += (lj > li) || (lj == li && j < i);   // stable desc sort rank
    }
    g_order[rank] = i;
    if (i < T_) {
        int c = 0;
        #pragma unroll 8
        for (int j = 0; j < B_; j++) c += (lens[j] > i);
        g_nvalid[i] = c;
    }
}

__global__ void k_gather(const float* __restrict__ enc) {
    int b = blockIdx.x;
    int o = g_order[b];
    ((float4*)g_enc)[b*128 + threadIdx.x] = ((const float4*)enc)[o*128 + threadIdx.x];
}

__global__ void k_buildWc1(const float* __restrict__ Wd, const float* __restrict__ bd,
                           const float* __restrict__ Wf, const float* __restrict__ bf) {
    int n = blockIdx.x;  // 0..1023
    const float* src = (n < 512) ? (Wd + (size_t)n*512) : (Wf + (size_t)(n-512)*512);
    ((float4*)(g_Wc1 + (size_t)n*512))[threadIdx.x] = ((const float4*)src)[threadIdx.x];
    if (threadIdx.x == 0) g_bc1[n] = (n < 512) ? bd[n] : bf[n-512];
}

__global__ void k_buildWbig(const float* __restrict__ Wih, const float* __restrict__ bih,
                            const float* __restrict__ Whh, const float* __restrict__ bhh) {
    int r = blockIdx.x;  // 0..2047
    const float4* ih = (const float4*)(Wih + (size_t)r*1024);
    const float4* hh = (const float4*)(Whh + (size_t)r*512);
    float4* dst = (float4*)(g_Wbig + (size_t)r*1536);
    #pragma unroll
    for (int it = 0; it < 3; it++) {
        int k4 = threadIdx.x + 128*it;   // 0..383
        dst[k4] = (k4 < 256) ? ih[k4] : hh[k4-256];
    }
    if (threadIdx.x == 0) g_bbig[r] = bih[r] + bhh[r];
}

// transpose g_att1 (128x512) -> g_att1T (512x128)
__global__ void k_transpose() {
    __shared__ float tile[32][33];
    int c0 = blockIdx.x * 32;    // col of att1
    int r0 = blockIdx.y * 32;    // row of att1
    int tx = threadIdx.x, ty = threadIdx.y;  // (32, 8)
    #pragma unroll
    for (int r = 0; r < 4; r++)
        tile[ty + 8*r][tx] = g_att1[(r0 + ty + 8*r)*512 + c0 + tx];
    __syncthreads();
    #pragma unroll
    for (int r = 0; r < 4; r++)
        g_att1T[(c0 + ty + 8*r)*B_ + r0 + tx] = tile[tx][ty + 8*r];
}

// ---------------- generic NT GEMM, C[M,N] = A[M,K] @ W[N,K]^T + bias ----------------
// EPI 0: plain (prep, no validity)       EPI 1: att2gate (sigmoid cols>=512, tile-skip)
// EPI 2: gates (tile-skip)               EPI 3: preds -> d_out[r,t,:], zero invalid rows
template<int TM, int TN, int EPI>
__global__ void __launch_bounds__(256) k_gemm(
    const float* __restrict__ A, const float* __restrict__ W,
    const float* __restrict__ bias, float* __restrict__ out,
    int K, int t, int ldc)
{
    constexpr int BM = TM*16, BN = TN*16;
    __shared__ float As[16][BM+4];
    __shared__ float Bs[16][BN+4];

    const int nv   = (t >= 0) ? g_nvalid[t] : B_;
    const int row0 = blockIdx.y * BM;
    const int col0 = blockIdx.x * BN;
    const int tid  = threadIdx.x;
    const int tm = tid >> 4, tn = tid & 15;

    if (row0 >= nv) {
        if (EPI == 3) {
            #pragma unroll
            for (int i = 0; i < TM; i++) {
                int r = row0 + tm*TM + i;
                #pragma unroll
                for (int j = 0; j < TN; j++)
                    out[(size_t)r*TV_ + (size_t)t*V_ + (col0 + tn*TN + j)] = 0.f;
            }
        }
        return;
    }

    constexpr int KVA = 16/TM;
    const int ar = tid / KVA;
    const int ak = (tid % KVA) * TM;
    constexpr int KVW = 16/TN;
    const int wr = tid / KVW;
    const int wk = (tid % KVW) * TN;

    const float* Ap = A + (size_t)(row0 + ar)*K + ak;
    const float* Wp = W + (size_t)(col0 + wr)*K + wk;

    float acc[TM][TN];
    #pragma unroll
    for (int i = 0; i < TM; i++)
        #pragma unroll
        for (int j = 0; j < TN; j++) acc[i][j] = 0.f;

    for (int k0 = 0; k0 < K; k0 += 16) {
        float ra[TM], rw[TN];
        if constexpr (TM == 4) {
            float4 v = *(const float4*)(Ap + k0);
            ra[0]=v.x; ra[1]=v.y; ra[2]=v.z; ra[3]=v.w;
        } else {
            float2 v = *(const float2*)(Ap + k0);
            ra[0]=v.x; ra[1]=v.y;
        }
        if constexpr (TN == 4) {
            float4 v = *(const float4*)(Wp + k0);
            rw[0]=v.x; rw[1]=v.y; rw[2]=v.z; rw[3]=v.w;
        } else {
            float2 v = *(const float2*)(Wp + k0);
            rw[0]=v.x; rw[1]=v.y;
        }
        __syncthreads();
        #pragma unroll
        for (int u = 0; u < TM; u++) As[ak+u][ar] = ra[u];
        #pragma unroll
        for (int u = 0; u < TN; u++) Bs[wk+u][wr] = rw[u];
        __syncthreads();
        #pragma unroll
        for (int kk = 0; kk < 16; kk++) {
            float a[TM], b[TN];
            #pragma unroll
            for (int i = 0; i < TM; i++) a[i] = As[kk][tm*TM + i];
            #pragma unroll
            for (int j = 0; j < TN; j++) b[j] = Bs[kk][tn*TN + j];
            #pragma unroll
            for (int i = 0; i < TM; i++)
                #pragma unroll
                for (int j = 0; j < TN; j++)
                    acc[i][j] = fmaf(a[i], b[j], acc[i][j]);
        }
    }

    #pragma unroll
    for (int i = 0; i < TM; i++) {
        int r = row0 + tm*TM + i;
        #pragma unroll
        for (int j = 0; j < TN; j++) {
            int cdx = col0 + tn*TN + j;
            float v = acc[i][j] + bias[cdx];
            if (EPI == 1 && cdx >= 512) v = 1.f/(1.f + expf(-v));
            if (EPI == 3) {
                if (r >= nv) v = 0.f;
                out[(size_t)r*TV_ + (size_t)t*V_ + cdx] = v;
            } else {
                out[(size_t)r*ldc + cdx] = v;
            }
        }
    }
}

// ---------------- attention + xcat assembly (one CTA per valid row) ----------------
__global__ void k_attn(const int* __restrict__ caps, const float* __restrict__ emb,
                       const float* __restrict__ wfull, const float* __restrict__ bfull,
                       int t)
{
    int i = blockIdx.x;
    int nv = g_nvalid[t];
    if (i >= nv) return;

    __shared__ float s_att2[512];
    __shared__ float s_wf[512];
    __shared__ float s_red[128];
    __shared__ float s_al[128];
    int tid = threadIdx.x;  // 128 threads

    #pragma unroll
    for (int u = 0; u < 4; u++) {
        s_att2[tid + 128*u] = g_att2gate[i*1024 + tid + 128*u];
        s_wf[tid + 128*u]   = wfull[tid + 128*u];
    }
    __syncthreads();

    // scores[i, j] for j = tid
    float s;
    int j = tid;
    if (j < nv) {
        s = 0.f;
        #pragma unroll 4
        for (int k = 0; k < 512; k++) {
            float x = g_att1T[k*B_ + j] + s_att2[k];
            s = fmaf(fmaxf(x, 0.f), s_wf[k], s);
        }
        s += bfull[0];
    } else {
        s = -3.0e38f;
    }

    // softmax over valid j
    s_red[tid] = s; __syncthreads();
    for (int off = 64; off > 0; off >>= 1) {
        if (tid < off) s_red[tid] = fmaxf(s_red[tid], s_red[tid+off]);
        __syncthreads();
    }
    float mx = s_red[0];
    __syncthreads();
    float e = (j < nv) ? expf(s - mx) : 0.f;
    s_red[tid] = e; __syncthreads();
    for (int off = 64; off > 0; off >>= 1) {
        if (tid < off) s_red[tid] += s_red[tid+off];
        __syncthreads();
    }
    float inv = 1.f / s_red[0];
    s_al[tid] = e * inv;
    __syncthreads();

    // awe = alpha @ enc (4 cols per thread)
    float aw[4] = {0.f, 0.f, 0.f, 0.f};
    for (int jj = 0; jj < nv; jj++) {
        float a = s_al[jj];
        #pragma unroll
        for (int u = 0; u < 4; u++)
            aw[u] = fmaf(a, g_enc[jj*512 + tid + 128*u], aw[u]);
    }

    // xcat = [emb | gate*awe | h]
    int cap = caps[g_order[i]*T_ + t];
    #pragma unroll
    for (int u = 0; u < 4; u++) {
        int k = tid + 128*u;
        float gt = g_att2gate[i*1024 + 512 + k];
        g_xcat[i*1536 + 512 + k]  = gt * aw[u];
        g_xcat[i*1536 + k]        = emb[(size_t)cap*512 + k];
        g_xcat[i*1536 + 1024 + k] = g_h[i*512 + k];
    }
}

// ---------------- LSTM pointwise ----------------
__global__ void k_lstm(int t) {
    int i = blockIdx.x;
    int nv = g_nvalid[t];
    if (i >= nv) return;
    int d = threadIdx.x;  // 512
    float gi = g_gates[i*2048 + d];
    float gf = g_gates[i*2048 + 512 + d];
    float gg = g_gates[i*2048 + 1024 + d];
    float go = g_gates[i*2048 + 1536 + d];
    gi = 1.f/(1.f + expf(-gi));
    gf = 1.f/(1.f + expf(-gf));
    go = 1.f/(1.f + expf(-go));
    gg = tanhf(gg);
    float c = gf * g_c[i*512 + d] + gi * gg;
    float h = go * tanhf(c);
    g_c[i*512 + d] = c;
    g_h[i*512 + d] = h;
}

// ---------------- host launch ----------------
extern "C" void kernel_launch(void* const* d_in, const int* in_sizes, int n_in,
                              void* d_out, int out_size) {
    const float* encoder_out = (const float*)d_in[0];
    const int*   caps        = (const int*)  d_in[1];
    const int*   capl        = (const int*)  d_in[2];
    const float* W_enc  = (const float*)d_in[3];
    const float* b_enc  = (const float*)d_in[4];
    const float* W_dec  = (const float*)d_in[5];
    const float* b_dec  = (const float*)d_in[6];
    const float* W_full = (const float*)d_in[7];
    const float* b_full = (const float*)d_in[8];
    const float* W_init_h = (const float*)d_in[9];
    const float* b_init_h = (const float*)d_in[10];
    const float* W_init_c = (const float*)d_in[11];
    const float* b_init_c = (const float*)d_in[12];
    const float* W_fbeta  = (const float*)d_in[13];
    const float* b_fbeta  = (const float*)d_in[14];
    const float* W_fc     = (const float*)d_in[15];
    const float* b_fc     = (const float*)d_in[16];
    const float* emb      = (const float*)d_in[17];
    const float* W_ih     = (const float*)d_in[18];
    const float* b_ih     = (const float*)d_in[19];
    const float* W_hh     = (const float*)d_in[20];
    const float* b_hh     = (const float*)d_in[21];
    float* out = (float*)d_out;

    // device-global addresses (host API, not a stream op — capture-safe)
    float *p_enc, *p_att1, *p_h, *p_c, *p_a2g, *p_xcat, *p_gates, *p_Wc1, *p_bc1, *p_Wbig, *p_bbig;
    cudaGetSymbolAddress((void**)&p_enc,   g_enc);
    cudaGetSymbolAddress((void**)&p_att1,  g_att1);
    cudaGetSymbolAddress((void**)&p_h,     g_h);
    cudaGetSymbolAddress((void**)&p_c,     g_c);
    cudaGetSymbolAddress((void**)&p_a2g,   g_att2gate);
    cudaGetSymbolAddress((void**)&p_xcat,  g_xcat);
    cudaGetSymbolAddress((void**)&p_gates, g_gates);
    cudaGetSymbolAddress((void**)&p_Wc1,   g_Wc1);
    cudaGetSymbolAddress((void**)&p_bc1,   g_bc1);
    cudaGetSymbolAddress((void**)&p_Wbig,  g_Wbig);
    cudaGetSymbolAddress((void**)&p_bbig,  g_bbig);

    // prep
    k_prep<<<1, 128>>>(capl);
    k_gather<<<128, 128>>>(encoder_out);
    k_buildWc1<<<1024, 128>>>(W_dec, b_dec, W_fbeta, b_fbeta);
    k_buildWbig<<<2048, 128>>>(W_ih, b_ih, W_hh, b_hh);
    k_gemm<2,2,0><<<dim3(16,4), 256>>>(p_enc, W_init_h, b_init_h, p_h,    512, -1, 512);
    k_gemm<2,2,0><<<dim3(16,4), 256>>>(p_enc, W_init_c, b_init_c, p_c,    512, -1, 512);
    k_gemm<2,2,0><<<dim3(16,4), 256>>>(p_enc, W_enc,    b_enc,    p_att1, 512, -1, 512);
    k_transpose<<<dim3(16,4), dim3(32,8)>>>();

    // time steps
    for (int t = 0; t < T_; t++) {
        k_gemm<2,2,1><<<dim3(32,4), 256>>>(p_h,    p_Wc1,  p_bc1,  p_a2g,   512,  t, 1024);
        k_attn<<<128, 128>>>(caps, emb, W_full, b_full, t);
        k_gemm<2,4,2><<<dim3(32,4), 256>>>(p_xcat, p_Wbig, p_bbig, p_gates, 1536, t, 2048);
        k_lstm<<<128, 512>>>(t);
        k_gemm<4,4,3><<<dim3(64,2), 256>>>(p_h,    W_fc,   b_fc,   out,     512,  t, 0);
    }
}

// round 3
// speedup vs baseline: 1.1019x; 1.1019x over previous
#include <cuda_runtime.h>
#include <cuda_bf16.h>
#include <math.h>
#include <stdint.h>

#define B_  128
#define T_  96
#define V_  4096
#define TV_ (T_*V_)

typedef __nv_bfloat16 bf16;

// ---------------- device scratch (static; no runtime alloc) ----------------
__device__ __align__(16) float g_enc[B_*512];
__device__ __align__(16) float g_att1[B_*512];
__device__ __align__(16) float g_att1T[512*B_];
__device__ __align__(16) float g_h[B_*512];          // fp32 h (init only)
__device__ __align__(16) float g_c[B_*512];
__device__ __align__(16) float g_att2gate[B_*1024];  // [att2 | sigmoid gate]
__device__ __align__(16) float g_gates[B_*2048];
__device__ __align__(16) float g_Wc1[1024*512];      // fp32 staging [W_dec;W_fbeta]
__device__ __align__(16) float g_bc1[1024];
__device__ __align__(16) float g_Wbig[2048*1536];    // fp32 staging [W_ih|W_hh]
__device__ __align__(16) float g_bbig[2048];
// bf16 split operands (A2 = [Ah|Ah|Al], W2 = [Wh|Wl|Wh])
__device__ __align__(16) bf16  g_h2[B_*1536];
__device__ __align__(16) bf16  g_xcat2[B_*4608];
__device__ __align__(16) bf16  g_Wc1b[1024*1536];
__device__ __align__(16) bf16  g_Wbigb[2048*4608];
__device__ __align__(16) bf16  g_Wfcb[4096*1536];
__device__ int g_order[B_];
__device__ int g_nvalid[T_];

// ---------------- helpers ----------------
__device__ __forceinline__ uint32_t sptr(const void* p) {
    return (uint32_t)__cvta_generic_to_shared(p);
}
__device__ __forceinline__ void split2(float x, bf16& hi, bf16& lo) {
    hi = __float2bfloat16(x);
    lo = __float2bfloat16(x - __bfloat162float(hi));
}

// ---------------- prep kernels ----------------
__global__ void k_prep(const int* __restrict__ capl) {
    __shared__ int lens[B_];
    int i = threadIdx.x;
    lens[i] = capl[i];
    __syncthreads();
    int li = lens[i];
    int rank = 0;
    #pragma unroll 8
    for (int j = 0; j < B_; j++) {
        int lj = lens[j];
        rank += (lj > li) || (lj == li && j < i);
    }
    g_order[rank] = i;
    if (i < T_) {
        int c = 0;
        #pragma unroll 8
        for (int j = 0; j < B_; j++) c += (lens[j] > i);
        g_nvalid[i] = c;
    }
}

__global__ void k_gather(const float* __restrict__ enc) {
    int b = blockIdx.x;
    int o = g_order[b];
    ((float4*)g_enc)[b*128 + threadIdx.x] = ((const float4*)enc)[o*128 + threadIdx.x];
}

__global__ void k_buildWc1(const float* __restrict__ Wd, const float* __restrict__ bd,
                           const float* __restrict__ Wf, const float* __restrict__ bf) {
    int n = blockIdx.x;
    const float* src = (n < 512) ? (Wd + (size_t)n*512) : (Wf + (size_t)(n-512)*512);
    ((float4*)(g_Wc1 + (size_t)n*512))[threadIdx.x] = ((const float4*)src)[threadIdx.x];
    if (threadIdx.x == 0) g_bc1[n] = (n < 512) ? bd[n] : bf[n-512];
}

__global__ void k_buildWbig(const float* __restrict__ Wih, const float* __restrict__ bih,
                            const float* __restrict__ Whh, const float* __restrict__ bhh) {
    int r = blockIdx.x;
    const float4* ih = (const float4*)(Wih + (size_t)r*1024);
    const float4* hh = (const float4*)(Whh + (size_t)r*512);
    float4* dst = (float4*)(g_Wbig + (size_t)r*1536);
    #pragma unroll
    for (int it = 0; it < 3; it++) {
        int k4 = threadIdx.x + 128*it;
        dst[k4] = (k4 < 256) ? ih[k4] : hh[k4-256];
    }
    if (threadIdx.x == 0) g_bbig[r] = bih[r] + bhh[r];
}

// fp32 [N][K] -> bf16 [N][3K] = [Wh | Wl | Wh]
template<int K>
__global__ void k_cvt3(const float* __restrict__ src, bf16* __restrict__ dst) {
    int n = blockIdx.x;
    const float* s = src + (size_t)n*K;
    bf16* d = dst + (size_t)n*(3*K);
    for (int k = threadIdx.x; k < K; k += 128) {
        bf16 hi, lo;
        split2(s[k], hi, lo);
        d[k] = hi; d[K + k] = lo; d[2*K + k] = hi;
    }
}

// h (fp32) -> g_h2 = [Hh | Hh | Hl]
__global__ void k_split_h() {
    int i = blockIdx.x, d = threadIdx.x;
    bf16 hi, lo;
    split2(g_h[i*512 + d], hi, lo);
    g_h2[i*1536 + d] = hi;
    g_h2[i*1536 + 512 + d] = hi;
    g_h2[i*1536 + 1024 + d] = lo;
}

__global__ void k_transpose() {
    __shared__ float tile[32][33];
    int c0 = blockIdx.x * 32, r0 = blockIdx.y * 32;
    int tx = threadIdx.x, ty = threadIdx.y;
    #pragma unroll
    for (int r = 0; r < 4; r++)
        tile[ty + 8*r][tx] = g_att1[(r0 + ty + 8*r)*512 + c0 + tx];
    __syncthreads();
    #pragma unroll
    for (int r = 0; r < 4; r++)
        g_att1T[(c0 + ty + 8*r)*B_ + r0 + tx] = tile[tx][ty + 8*r];
}

// ---------------- fp32 GEMM (prep only, runs once) ----------------
__global__ void __launch_bounds__(256) k_gemm32(
    const float* __restrict__ A, const float* __restrict__ W,
    const float* __restrict__ bias, float* __restrict__ out, int K, int ldc)
{
    __shared__ float As[16][36];
    __shared__ float Bs[16][36];
    const int row0 = blockIdx.y * 32, col0 = blockIdx.x * 32;
    const int tid = threadIdx.x;
    const int tm = tid >> 4, tn = tid & 15;
    const int ar = tid >> 3, ak = (tid & 7) * 2;
    const float* Ap = A + (size_t)(row0 + ar)*K + ak;
    const float* Wp = W + (size_t)(col0 + ar)*K + ak;
    float acc[2][2] = {{0,0},{0,0}};
    for (int k0 = 0; k0 < K; k0 += 16) {
        float2 va = *(const float2*)(Ap + k0);
        float2 vw = *(const float2*)(Wp + k0);
        __syncthreads();
        As[ak][ar] = va.x; As[ak+1][ar] = va.y;
        Bs[ak][ar] = vw.x; Bs[ak+1][ar] = vw.y;
        __syncthreads();
        #pragma unroll
        for (int kk = 0; kk < 16; kk++) {
            float a0 = As[kk][tm*2], a1 = As[kk][tm*2+1];
            float b0 = Bs[kk][tn*2], b1 = Bs[kk][tn*2+1];
            acc[0][0] = fmaf(a0, b0, acc[0][0]);
            acc[0][1] = fmaf(a0, b1, acc[0][1]);
            acc[1][0] = fmaf(a1, b0, acc[1][0]);
            acc[1][1] = fmaf(a1, b1, acc[1][1]);
        }
    }
    #pragma unroll
    for (int i = 0; i < 2; i++)
        #pragma unroll
        for (int j = 0; j < 2; j++) {
            int r = row0 + tm*2 + i, cdx = col0 + tn*2 + j;
            out[(size_t)r*ldc + cdx] = acc[i][j] + bias[cdx];
        }
}

// ---------------- bf16 tensor-core NT GEMM ----------------
// C[M,N] = A2[M,Keff] @ W2[N,Keff]^T + bias, fp32 accum.
// BM=32, BN=4*WN, 8 warps (2 M x 4 N), warp tile 16 x WN.
// EPI 1: att2gate (sigmoid cols>=512)  EPI 2: gates  EPI 3: preds -> d_out
template<int WN, int EPI>
__global__ void __launch_bounds__(256) k_mma(
    const bf16* __restrict__ A2, const bf16* __restrict__ W2,
    const float* __restrict__ bias, float* __restrict__ out,
    int Keff, int t, int ldc)
{
    constexpr int BN = 4*WN;
    constexpr int NBLK = WN/8;     // n8 blocks per warp
    constexpr int NP   = NBLK/2;   // ldmatrix.x4 pairs for B
    constexpr int BIT  = BN/32;    // B global-load iterations (uint2 per thread)

    __shared__ __align__(16) bf16 sA[2][32*40];
    __shared__ __align__(16) bf16 sB[2][BN*40];

    const int nv   = (t >= 0) ? g_nvalid[t] : B_;
    const int row0 = blockIdx.y * 32;
    const int col0 = blockIdx.x * BN;
    const int tid  = threadIdx.x;

    if (row0 >= nv) {
        if (EPI == 3) {
            float4 z = make_float4(0.f, 0.f, 0.f, 0.f);
            for (int x = tid*4; x < 32*BN; x += 1024) {
                int r = x / BN, cI = x % BN;
                *(float4*)(out + (size_t)(row0 + r)*TV_ + (size_t)t*V_ + col0 + cI) = z;
            }
        }
        return;
    }

    const int warp = tid >> 5, lane = tid & 31;
    const int mw = warp & 1, nw = warp >> 1;

    // global->reg staging indices
    const int arow = tid >> 3, aseg = tid & 7;
    const bf16* Ag = A2 + (size_t)(row0 + arow)*Keff + aseg*4;

    // ldmatrix smem offsets (bf16 units)
    const int a_m = mw*16 + (lane & 7) + ((lane >> 3) & 1)*8;
    const int a_k = ((lane >> 4) & 1)*8;
    const int aoff = a_m*40 + a_k;
    int boff[NP];
    #pragma unroll
    for (int p = 0; p < NP; p++) {
        int n = nw*WN + p*16 + (lane & 7) + ((lane >> 4) & 1)*8;
        int kk = ((lane >> 3) & 1)*8;
        boff[p] = n*40 + kk;
    }

    float acc[NBLK][4];
    #pragma unroll
    for (int b = 0; b < NBLK; b++)
        #pragma unroll
        for (int j = 0; j < 4; j++) acc[b][j] = 0.f;

    const int S = Keff >> 5;   // 32-wide K slabs

    // prefetch slab 0
    uint2 rA = *(const uint2*)Ag;
    uint2 rB[BIT];
    #pragma unroll
    for (int i = 0; i < BIT; i++) {
        int idx = tid + i*256;
        rB[i] = *(const uint2*)(W2 + (size_t)(col0 + (idx >> 3))*Keff + (idx & 7)*4);
    }
    *(uint2*)(&sA[0][arow*40 + aseg*4]) = rA;
    #pragma unroll
    for (int i = 0; i < BIT; i++) {
        int idx = tid + i*256;
        *(uint2*)(&sB[0][(idx >> 3)*40 + (idx & 7)*4]) = rB[i];
    }
    __syncthreads();

    for (int s = 0; s < S; s++) {
        const int nxt = s + 1;
        if (nxt < S) {
            rA = *(const uint2*)(Ag + nxt*32);
            #pragma unroll
            for (int i = 0; i < BIT; i++) {
                int idx = tid + i*256;
                rB[i] = *(const uint2*)(W2 + (size_t)(col0 + (idx >> 3))*Keff + nxt*32 + (idx & 7)*4);
            }
        }
        const int buf = s & 1;
        #pragma unroll
        for (int k16 = 0; k16 < 2; k16++) {
            uint32_t a0, a1, a2, a3;
            uint32_t ad = sptr(&sA[buf][aoff + k16*16]);
            asm volatile("ldmatrix.sync.aligned.m8n8.x4.shared.b16 {%0,%1,%2,%3}, [%4];"
                         : "=r"(a0), "=r"(a1), "=r"(a2), "=r"(a3) : "r"(ad));
            #pragma unroll
            for (int p = 0; p < NP; p++) {
                uint32_t b0, b1, b2, b3;
                uint32_t bd = sptr(&sB[buf][boff[p] + k16*16]);
                asm volatile("ldmatrix.sync.aligned.m8n8.x4.shared.b16 {%0,%1,%2,%3}, [%4];"
                             : "=r"(b0), "=r"(b1), "=r"(b2), "=r"(b3) : "r"(bd));
                asm volatile("mma.sync.aligned.m16n8k16.row.col.f32.bf16.bf16.f32 "
                             "{%0,%1,%2,%3},{%4,%5,%6,%7},{%8,%9},{%0,%1,%2,%3};"
                             : "+f"(acc[2*p][0]), "+f"(acc[2*p][1]), "+f"(acc[2*p][2]), "+f"(acc[2*p][3])
                             : "r"(a0), "r"(a1), "r"(a2), "r"(a3), "r"(b0), "r"(b1));
                asm volatile("mma.sync.aligned.m16n8k16.row.col.f32.bf16.bf16.f32 "
                             "{%0,%1,%2,%3},{%4,%5,%6,%7},{%8,%9},{%0,%1,%2,%3};"
                             : "+f"(acc[2*p+1][0]), "+f"(acc[2*p+1][1]), "+f"(acc[2*p+1][2]), "+f"(acc[2*p+1][3])
                             : "r"(a0), "r"(a1), "r"(a2), "r"(a3), "r"(b2), "r"(b3));
            }
        }
        if (nxt < S) {
            *(uint2*)(&sA[buf ^ 1][arow*40 + aseg*4]) = rA;
            #pragma unroll
            for (int i = 0; i < BIT; i++) {
                int idx = tid + i*256;
                *(uint2*)(&sB[buf ^ 1][(idx >> 3)*40 + (idx & 7)*4]) = rB[i];
            }
        }
        __syncthreads();
    }

    // epilogue
    const int g = lane >> 2, tg = lane & 3;
    const int rbase = row0 + mw*16;
    #pragma unroll
    for (int b = 0; b < NBLK; b++) {
        int ncol = col0 + nw*WN + b*8 + tg*2;
        float v00 = acc[b][0] + bias[ncol];
        float v01 = acc[b][1] + bias[ncol+1];
        float v10 = acc[b][2] + bias[ncol];
        float v11 = acc[b][3] + bias[ncol+1];
        if (EPI == 1 && ncol >= 512) {
            v00 = 1.f/(1.f + expf(-v00));
            v01 = 1.f/(1.f + expf(-v01));
            v10 = 1.f/(1.f + expf(-v10));
            v11 = 1.f/(1.f + expf(-v11));
        }
        int r0 = rbase + g, r1 = rbase + g + 8;
        if (EPI == 3) {
            float2 z = make_float2(0.f, 0.f);
            float2 w0 = (r0 < nv) ? make_float2(v00, v01) : z;
            float2 w1 = (r1 < nv) ? make_float2(v10, v11) : z;
            *(float2*)(out + (size_t)r0*TV_ + (size_t)t*V_ + ncol) = w0;
            *(float2*)(out + (size_t)r1*TV_ + (size_t)t*V_ + ncol) = w1;
        } else {
            *(float2*)(out + (size_t)r0*ldc + ncol) = make_float2(v00, v01);
            *(float2*)(out + (size_t)r1*ldc + ncol) = make_float2(v10, v11);
        }
    }
}

// ---------------- attention + xcat2 assembly ----------------
__global__ void k_attn(const int* __restrict__ caps, const float* __restrict__ emb,
                       const float* __restrict__ wfull, const float* __restrict__ bfull,
                       int t)
{
    int i = blockIdx.x;
    int nv = g_nvalid[t];
    if (i >= nv) return;

    __shared__ float s_att2[512];
    __shared__ float s_wf[512];
    __shared__ float s_red[128];
    __shared__ float s_al[128];
    int tid = threadIdx.x;

    #pragma unroll
    for (int u = 0; u < 4; u++) {
        s_att2[tid + 128*u] = g_att2gate[i*1024 + tid + 128*u];
        s_wf[tid + 128*u]   = wfull[tid + 128*u];
    }
    __syncthreads();

    float s;
    int j = tid;
    if (j < nv) {
        s = 0.f;
        #pragma unroll 4
        for (int k = 0; k < 512; k++) {
            float x = g_att1T[k*B_ + j] + s_att2[k];
            s = fmaf(fmaxf(x, 0.f), s_wf[k], s);
        }
        s += bfull[0];
    } else {
        s = -3.0e38f;
    }

    s_red[tid] = s; __syncthreads();
    for (int off = 64; off > 0; off >>= 1) {
        if (tid < off) s_red[tid] = fmaxf(s_red[tid], s_red[tid+off]);
        __syncthreads();
    }
    float mx = s_red[0];
    __syncthreads();
    float e = (j < nv) ? expf(s - mx) : 0.f;
    s_red[tid] = e; __syncthreads();
    for (int off = 64; off > 0; off >>= 1) {
        if (tid < off) s_red[tid] += s_red[tid+off];
        __syncthreads();
    }
    float inv = 1.f / s_red[0];
    s_al[tid] = e * inv;
    __syncthreads();

    float aw[4] = {0.f, 0.f, 0.f, 0.f};
    for (int jj = 0; jj < nv; jj++) {
        float a = s_al[jj];
        #pragma unroll
        for (int u = 0; u < 4; u++)
            aw[u] = fmaf(a, g_enc[jj*512 + tid + 128*u], aw[u]);
    }

    // xcat2 row i: X = [emb(512) | gate*awe(512) | h(512)], stored [Xh|Xh|Xl]
    int cap = caps[g_order[i]*T_ + t];
    bf16* xr = g_xcat2 + (size_t)i*4608;
    #pragma unroll
    for (int u = 0; u < 4; u++) {
        int k = tid + 128*u;
        bf16 hi, lo;
        // emb
        split2(emb[(size_t)cap*512 + k], hi, lo);
        xr[k] = hi; xr[1536 + k] = hi; xr[3072 + k] = lo;
        // gated awe
        float gt = g_att2gate[i*1024 + 512 + k];
        split2(gt * aw[u], hi, lo);
        xr[512 + k] = hi; xr[1536 + 512 + k] = hi; xr[3072 + 512 + k] = lo;
        // h: copy from g_h2 ([Hh|Hh|Hl])
        bf16 hh = g_h2[i*1536 + k];
        bf16 hl = g_h2[i*1536 + 1024 + k];
        xr[1024 + k] = hh; xr[1536 + 1024 + k] = hh; xr[3072 + 1024 + k] = hl;
    }
}

// ---------------- LSTM pointwise + h split ----------------
__global__ void k_lstm(int t) {
    int i = blockIdx.x;
    int nv = g_nvalid[t];
    if (i >= nv) return;
    int d = threadIdx.x;
    float gi = g_gates[i*2048 + d];
    float gf = g_gates[i*2048 + 512 + d];
    float gg = g_gates[i*2048 + 1024 + d];
    float go = g_gates[i*2048 + 1536 + d];
    gi = 1.f/(1.f + expf(-gi));
    gf = 1.f/(1.f + expf(-gf));
    go = 1.f/(1.f + expf(-go));
    gg = tanhf(gg);
    float c = gf * g_c[i*512 + d] + gi * gg;
    float h = go * tanhf(c);
    g_c[i*512 + d] = c;
    bf16 hi, lo;
    split2(h, hi, lo);
    g_h2[i*1536 + d] = hi;
    g_h2[i*1536 + 512 + d] = hi;
    g_h2[i*1536 + 1024 + d] = lo;
}

// ---------------- host launch ----------------
extern "C" void kernel_launch(void* const* d_in, const int* in_sizes, int n_in,
                              void* d_out, int out_size) {
    const float* encoder_out = (const float*)d_in[0];
    const int*   caps        = (const int*)  d_in[1];
    const int*   capl        = (const int*)  d_in[2];
    const float* W_enc  = (const float*)d_in[3];
    const float* b_enc  = (const float*)d_in[4];
    const float* W_dec  = (const float*)d_in[5];
    const float* b_dec  = (const float*)d_in[6];
    const float* W_full = (const float*)d_in[7];
    const float* b_full = (const float*)d_in[8];
    const float* W_init_h = (const float*)d_in[9];
    const float* b_init_h = (const float*)d_in[10];
    const float* W_init_c = (const float*)d_in[11];
    const float* b_init_c = (const float*)d_in[12];
    const float* W_fbeta  = (const float*)d_in[13];
    const float* b_fbeta  = (const float*)d_in[14];
    const float* W_fc     = (const float*)d_in[15];
    const float* b_fc     = (const float*)d_in[16];
    const float* emb      = (const float*)d_in[17];
    const float* W_ih     = (const float*)d_in[18];
    const float* b_ih     = (const float*)d_in[19];
    const float* W_hh     = (const float*)d_in[20];
    const float* b_hh     = (const float*)d_in[21];
    float* out = (float*)d_out;

    float *p_enc, *p_att1, *p_h, *p_c, *p_a2g, *p_gates, *p_Wc1, *p_bc1, *p_Wbig, *p_bbig;
    bf16  *p_h2, *p_xcat2, *p_Wc1b, *p_Wbigb, *p_Wfcb;
    cudaGetSymbolAddress((void**)&p_enc,   g_enc);
    cudaGetSymbolAddress((void**)&p_att1,  g_att1);
    cudaGetSymbolAddress((void**)&p_h,     g_h);
    cudaGetSymbolAddress((void**)&p_c,     g_c);
    cudaGetSymbolAddress((void**)&p_a2g,   g_att2gate);
    cudaGetSymbolAddress((void**)&p_gates, g_gates);
    cudaGetSymbolAddress((void**)&p_Wc1,   g_Wc1);
    cudaGetSymbolAddress((void**)&p_bc1,   g_bc1);
    cudaGetSymbolAddress((void**)&p_Wbig,  g_Wbig);
    cudaGetSymbolAddress((void**)&p_bbig,  g_bbig);
    cudaGetSymbolAddress((void**)&p_h2,    g_h2);
    cudaGetSymbolAddress((void**)&p_xcat2, g_xcat2);
    cudaGetSymbolAddress((void**)&p_Wc1b,  g_Wc1b);
    cudaGetSymbolAddress((void**)&p_Wbigb, g_Wbigb);
    cudaGetSymbolAddress((void**)&p_Wfcb,  g_Wfcb);

    // ---- prep (once per launch) ----
    k_prep<<<1, 128>>>(capl);
    k_gather<<<128, 128>>>(encoder_out);
    k_buildWc1<<<1024, 128>>>(W_dec, b_dec, W_fbeta, b_fbeta);
    k_buildWbig<<<2048, 128>>>(W_ih, b_ih, W_hh, b_hh);
    k_cvt3<512> <<<1024, 128>>>(p_Wc1,  p_Wc1b);
    k_cvt3<1536><<<2048, 128>>>(p_Wbig, p_Wbigb);
    k_cvt3<512> <<<4096, 128>>>(W_fc,   p_Wfcb);
    k_gemm32<<<dim3(16,4), 256>>>(p_enc, W_init_h, b_init_h, p_h,    512, 512);
    k_gemm32<<<dim3(16,4), 256>>>(p_enc, W_init_c, b_init_c, p_c,    512, 512);
    k_gemm32<<<dim3(16,4), 256>>>(p_enc, W_enc,    b_enc,    p_att1, 512, 512);
    k_transpose<<<dim3(16,4), dim3(32,8)>>>();
    k_split_h<<<128, 512>>>();

    // ---- time steps ----
    for (int t = 0; t < T_; t++) {
        k_mma<16,1><<<dim3(16,4), 256>>>(p_h2,    p_Wc1b,  p_bc1,  p_a2g,   1536, t, 1024);
        k_attn<<<128, 128>>>(caps, emb, W_full, b_full, t);
        k_mma<16,2><<<dim3(32,4), 256>>>(p_xcat2, p_Wbigb, p_bbig, p_gates, 4608, t, 2048);
        k_lstm<<<128, 512>>>(t);
        k_mma<32,3><<<dim3(32,4), 256>>>(p_h2,    p_Wfcb,  b_fc,   out,     1536, t, 0);
    }
}

// round 4
// speedup vs baseline: 2.6899x; 2.4412x over previous
#include <cuda_runtime.h>
#include <cuda_bf16.h>
#include <math.h>
#include <stdint.h>

#define B_  128
#define T_  96
#define V_  4096
#define TV_ (T_*V_)
#define HB_ (B_*1536)

typedef __nv_bfloat16 bf16;

// ---------------- device scratch ----------------
__device__ __align__(16) float g_enc[B_*512];
__device__ __align__(16) float g_att1[B_*512];
__device__ __align__(16) float g_att1T[512*B_];
__device__ __align__(16) float g_h[B_*512];
__device__ __align__(16) float g_c[B_*512];
__device__ __align__(16) float g_att2gate[B_*1024];
__device__ __align__(16) float g_Wc1[1024*512];
__device__ __align__(16) float g_bc1[1024];
__device__ __align__(16) float g_Wbig[2048*1536];   // PERMUTED rows r=4d+q
__device__ __align__(16) float g_bbig[2048];
__device__ __align__(16) bf16  g_h2[2][HB_];        // ping-pong [Hh|Hh|Hl]
__device__ __align__(16) bf16  g_xcat2[B_*4608];
__device__ __align__(16) bf16  g_Wc1b[1024*1536];
__device__ __align__(16) bf16  g_Wbigb[2048*4608];
__device__ __align__(16) bf16  g_Wfcb[4096*1536];
__device__ int g_order[B_];
__device__ int g_nvalid[T_];

// ---------------- helpers ----------------
__device__ __forceinline__ uint32_t sptr(const void* p) {
    return (uint32_t)__cvta_generic_to_shared(p);
}
__device__ __forceinline__ void split2(float x, bf16& hi, bf16& lo) {
    hi = __float2bfloat16(x);
    lo = __float2bfloat16(x - __bfloat162float(hi));
}
__device__ __forceinline__ float sigm(float x){ return 1.f/(1.f+expf(-x)); }

#define CP16(d, s) asm volatile("cp.async.ca.shared.global [%0], [%1], 16;" :: "r"(d), "l"(s))
#define CPCOMMIT() asm volatile("cp.async.commit_group;")
#define CPWAIT1()  asm volatile("cp.async.wait_group 1;" ::: "memory")

// ---------------- prep kernels ----------------
__global__ void k_prep(const int* __restrict__ capl) {
    __shared__ int lens[B_];
    int i = threadIdx.x;
    lens[i] = capl[i];
    __syncthreads();
    int li = lens[i];
    int rank = 0;
    #pragma unroll 8
    for (int j = 0; j < B_; j++) {
        int lj = lens[j];
        rank += (lj > li) || (lj == li && j < i);
    }
    g_order[rank] = i;
    if (i < T_) {
        int c = 0;
        #pragma unroll 8
        for (int j = 0; j < B_; j++) c += (lens[j] > i);
        g_nvalid[i] = c;
    }
}

__global__ void k_gather(const float* __restrict__ enc) {
    int b = blockIdx.x;
    int o = g_order[b];
    ((float4*)g_enc)[b*128 + threadIdx.x] = ((const float4*)enc)[o*128 + threadIdx.x];
}

__global__ void k_buildWc1(const float* __restrict__ Wd, const float* __restrict__ bd,
                           const float* __restrict__ Wf, const float* __restrict__ bf) {
    int n = blockIdx.x;
    const float* src = (n < 512) ? (Wd + (size_t)n*512) : (Wf + (size_t)(n-512)*512);
    ((float4*)(g_Wc1 + (size_t)n*512))[threadIdx.x] = ((const float4*)src)[threadIdx.x];
    if (threadIdx.x == 0) g_bc1[n] = (n < 512) ? bd[n] : bf[n-512];
}

// permuted: dest row r=4d+q <- original row q*512+d of [W_ih | W_hh]
__global__ void k_buildWbig(const float* __restrict__ Wih, const float* __restrict__ bih,
                            const float* __restrict__ Whh, const float* __restrict__ bhh) {
    int r = blockIdx.x;
    int dd = r >> 2, q = r & 3;
    int s = q*512 + dd;
    const float4* ih = (const float4*)(Wih + (size_t)s*1024);
    const float4* hh = (const float4*)(Whh + (size_t)s*512);
    float4* dst = (float4*)(g_Wbig + (size_t)r*1536);
    #pragma unroll
    for (int it = 0; it < 3; it++) {
        int k4 = threadIdx.x + 128*it;
        dst[k4] = (k4 < 256) ? ih[k4] : hh[k4-256];
    }
    if (threadIdx.x == 0) g_bbig[r] = bih[s] + bhh[s];
}

template<int K>
__global__ void k_cvt3(const float* __restrict__ src, bf16* __restrict__ dst) {
    int n = blockIdx.x;
    const float* s = src + (size_t)n*K;
    bf16* d = dst + (size_t)n*(3*K);
    for (int k = threadIdx.x; k < K; k += 128) {
        bf16 hi, lo;
        split2(s[k], hi, lo);
        d[k] = hi; d[K + k] = lo; d[2*K + k] = hi;
    }
}

__global__ void k_split_h() {
    int i = blockIdx.x, d = threadIdx.x;
    bf16 hi, lo;
    split2(g_h[i*512 + d], hi, lo);
    g_h2[0][i*1536 + d] = hi;
    g_h2[0][i*1536 + 512 + d] = hi;
    g_h2[0][i*1536 + 1024 + d] = lo;
}

__global__ void k_transpose() {
    __shared__ float tile[32][33];
    int c0 = blockIdx.x * 32, r0 = blockIdx.y * 32;
    int tx = threadIdx.x, ty = threadIdx.y;
    #pragma unroll
    for (int r = 0; r < 4; r++)
        tile[ty + 8*r][tx] = g_att1[(r0 + ty + 8*r)*512 + c0 + tx];
    __syncthreads();
    #pragma unroll
    for (int r = 0; r < 4; r++)
        g_att1T[(c0 + ty + 8*r)*B_ + r0 + tx] = tile[tx][ty + 8*r];
}

// ---------------- fp32 GEMM (prep only) ----------------
__global__ void __launch_bounds__(256) k_gemm32(
    const float* __restrict__ A, const float* __restrict__ W,
    const float* __restrict__ bias, float* __restrict__ out, int K, int ldc)
{
    __shared__ float As[16][36];
    __shared__ float Bs[16][36];
    const int row0 = blockIdx.y * 32, col0 = blockIdx.x * 32;
    const int tid = threadIdx.x;
    const int tm = tid >> 4, tn = tid & 15;
    const int ar = tid >> 3, ak = (tid & 7) * 2;
    const float* Ap = A + (size_t)(row0 + ar)*K + ak;
    const float* Wp = W + (size_t)(col0 + ar)*K + ak;
    float acc[2][2] = {{0,0},{0,0}};
    for (int k0 = 0; k0 < K; k0 += 16) {
        float2 va = *(const float2*)(Ap + k0);
        float2 vw = *(const float2*)(Wp + k0);
        __syncthreads();
        As[ak][ar] = va.x; As[ak+1][ar] = va.y;
        Bs[ak][ar] = vw.x; Bs[ak+1][ar] = vw.y;
        __syncthreads();
        #pragma unroll
        for (int kk = 0; kk < 16; kk++) {
            float a0 = As[kk][tm*2], a1 = As[kk][tm*2+1];
            float b0 = Bs[kk][tn*2], b1 = Bs[kk][tn*2+1];
            acc[0][0] = fmaf(a0, b0, acc[0][0]);
            acc[0][1] = fmaf(a0, b1, acc[0][1]);
            acc[1][0] = fmaf(a1, b0, acc[1][0]);
            acc[1][1] = fmaf(a1, b1, acc[1][1]);
        }
    }
    #pragma unroll
    for (int i = 0; i < 2; i++)
        #pragma unroll
        for (int j = 0; j < 2; j++) {
            int r = row0 + tm*2 + i, cdx = col0 + tn*2 + j;
            out[(size_t)r*ldc + cdx] = acc[i][j] + bias[cdx];
        }
}

// ---------------- bf16 MMA GEMM, cp.async 3-stage, BM=32, BN=64 ----------------
template<int EPI>
__global__ void __launch_bounds__(256) k_mma(
    const bf16* __restrict__ A2, const bf16* __restrict__ W2,
    const float* __restrict__ bias, float* __restrict__ out,
    bf16* __restrict__ h2out, int Keff, int t, int ldc)
{
    __shared__ __align__(16) bf16 sA[3][32*72];
    __shared__ __align__(16) bf16 sB[3][64*72];

    const int nv   = (t >= 0) ? g_nvalid[t] : B_;
    const int row0 = blockIdx.y * 32;
    const int col0 = blockIdx.x * 64;
    const int tid  = threadIdx.x;

    if (row0 >= nv) {
        if (EPI == 3) {
            float4 z = make_float4(0.f, 0.f, 0.f, 0.f);
            for (int x = tid; x < 512; x += 256) {
                int r = x >> 4, c4 = (x & 15) * 4;
                *(float4*)(out + (size_t)(row0 + r)*TV_ + (size_t)t*V_ + col0 + c4) = z;
            }
        }
        return;
    }

    const int warp = tid >> 5, lane = tid & 31;
    const int mw = warp & 1, nw = warp >> 1;

    const int ar = tid >> 3, ac = tid & 7;
    const bf16* a_src = A2 + (size_t)(row0 + ar)*Keff + ac*8;
    const uint32_t a_dst = sptr(&sA[0][0]) + (ar*72 + ac*8)*2;
    const int br0 = tid >> 3,         bc0 = tid & 7;
    const int br1 = (tid + 256) >> 3, bc1 = tid & 7;
    const bf16* b_src0 = W2 + (size_t)(col0 + br0)*Keff + bc0*8;
    const bf16* b_src1 = W2 + (size_t)(col0 + br1)*Keff + bc1*8;
    const uint32_t b_dst0 = sptr(&sB[0][0]) + (br0*72 + bc0*8)*2;
    const uint32_t b_dst1 = sptr(&sB[0][0]) + (br1*72 + bc1*8)*2;

    auto ld = [&](int st, int s) {
        CP16(a_dst  + st*4608, a_src  + s*64);
        CP16(b_dst0 + st*9216, b_src0 + s*64);
        CP16(b_dst1 + st*9216, b_src1 + s*64);
    };

    const int a_m = mw*16 + (lane & 7) + ((lane >> 3) & 1)*8;
    const int a_k = ((lane >> 4) & 1)*8;
    const int aoff = a_m*72 + a_k;
    const int b_n = nw*16 + (lane & 7) + ((lane >> 4) & 1)*8;
    const int b_k = ((lane >> 3) & 1)*8;
    const int boff = b_n*72 + b_k;

    float acc[2][4];
    #pragma unroll
    for (int b = 0; b < 2; b++)
        #pragma unroll
        for (int j = 0; j < 4; j++) acc[b][j] = 0.f;

    const int S = Keff >> 6;
    ld(0, 0); CPCOMMIT();
    ld(1, 1); CPCOMMIT();

    for (int s = 0; s < S; s++) {
        CPWAIT1();
        __syncthreads();
        const int buf = s % 3;
        #pragma unroll
        for (int k16 = 0; k16 < 4; k16++) {
            uint32_t a0, a1, a2, a3;
            uint32_t ad = sptr(&sA[buf][aoff + k16*16]);
            asm volatile("ldmatrix.sync.aligned.m8n8.x4.shared.b16 {%0,%1,%2,%3}, [%4];"
                         : "=r"(a0), "=r"(a1), "=r"(a2), "=r"(a3) : "r"(ad));
            uint32_t b0, b1, b2, b3;
            uint32_t bd = sptr(&sB[buf][boff + k16*16]);
            asm volatile("ldmatrix.sync.aligned.m8n8.x4.shared.b16 {%0,%1,%2,%3}, [%4];"
                         : "=r"(b0), "=r"(b1), "=r"(b2), "=r"(b3) : "r"(bd));
            asm volatile("mma.sync.aligned.m16n8k16.row.col.f32.bf16.bf16.f32 "
                         "{%0,%1,%2,%3},{%4,%5,%6,%7},{%8,%9},{%0,%1,%2,%3};"
                         : "+f"(acc[0][0]), "+f"(acc[0][1]), "+f"(acc[0][2]), "+f"(acc[0][3])
                         : "r"(a0), "r"(a1), "r"(a2), "r"(a3), "r"(b0), "r"(b1));
            asm volatile("mma.sync.aligned.m16n8k16.row.col.f32.bf16.bf16.f32 "
                         "{%0,%1,%2,%3},{%4,%5,%6,%7},{%8,%9},{%0,%1,%2,%3};"
                         : "+f"(acc[1][0]), "+f"(acc[1][1]), "+f"(acc[1][2]), "+f"(acc[1][3])
                         : "r"(a0), "r"(a1), "r"(a2), "r"(a3), "r"(b2), "r"(b3));
        }
        int nxt = s + 2;
        if (nxt < S) ld(nxt % 3, nxt);
        CPCOMMIT();
    }

    const int g = lane >> 2, tg = lane & 3;
    const int rbase = row0 + mw*16;

    if (EPI == 2) {
        #pragma unroll
        for (int b = 0; b < 2; b++) {
            int ncol = col0 + nw*16 + b*8 + tg*2;
            float v00 = acc[b][0] + bias[ncol];
            float v01 = acc[b][1] + bias[ncol+1];
            float v10 = acc[b][2] + bias[ncol];
            float v11 = acc[b][3] + bias[ncol+1];
            float p00 = __shfl_xor_sync(0xffffffffu, v00, 1);
            float p01 = __shfl_xor_sync(0xffffffffu, v01, 1);
            float p10 = __shfl_xor_sync(0xffffffffu, v10, 1);
            float p11 = __shfl_xor_sync(0xffffffffu, v11, 1);
            if (!(lane & 1)) {
                int d = ncol >> 2;
                int r0 = rbase + g, r1 = r0 + 8;
                {
                    float gi = sigm(v00), gf = sigm(v01);
                    float gg = tanhf(p00), go = sigm(p01);
                    float c = gf * g_c[r0*512 + d] + gi * gg;
                    float h = go * tanhf(c);
                    g_c[r0*512 + d] = c;
                    bf16 hh, hl; split2(h, hh, hl);
                    h2out[r0*1536 + d] = hh;
                    h2out[r0*1536 + 512 + d] = hh;
                    h2out[r0*1536 + 1024 + d] = hl;
                }
                {
                    float gi = sigm(v10), gf = sigm(v11);
                    float gg = tanhf(p10), go = sigm(p11);
                    float c = gf * g_c[r1*512 + d] + gi * gg;
                    float h = go * tanhf(c);
                    g_c[r1*512 + d] = c;
                    bf16 hh, hl; split2(h, hh, hl);
                    h2out[r1*1536 + d] = hh;
                    h2out[r1*1536 + 512 + d] = hh;
                    h2out[r1*1536 + 1024 + d] = hl;
                }
            }
        }
        return;
    }

    #pragma unroll
    for (int b = 0; b < 2; b++) {
        int ncol = col0 + nw*16 + b*8 + tg*2;
        float v00 = acc[b][0] + bias[ncol];
        float v01 = acc[b][1] + bias[ncol+1];
        float v10 = acc[b][2] + bias[ncol];
        float v11 = acc[b][3] + bias[ncol+1];
        if (EPI == 1 && ncol >= 512) {
            v00 = sigm(v00); v01 = sigm(v01);
            v10 = sigm(v10); v11 = sigm(v11);
        }
        int r0 = rbase + g, r1 = r0 + 8;
        if (EPI == 3) {
            float2 z = make_float2(0.f, 0.f);
            float2 w0 = (r0 < nv) ? make_float2(v00, v01) : z;
            float2 w1 = (r1 < nv) ? make_float2(v10, v11) : z;
            *(float2*)(out + (size_t)r0*TV_ + (size_t)t*V_ + ncol) = w0;
            *(float2*)(out + (size_t)r1*TV_ + (size_t)t*V_ + ncol) = w1;
        } else {
            *(float2*)(out + (size_t)r0*ldc + ncol) = make_float2(v00, v01);
            *(float2*)(out + (size_t)r1*ldc + ncol) = make_float2(v10, v11);
        }
    }
}

// ---------------- attention: 2 rows/CTA, 512 threads ----------------
__global__ void __launch_bounds__(512) k_attn(
    const int* __restrict__ caps, const float* __restrict__ emb,
    const float* __restrict__ wfull, const float* __restrict__ bfull,
    int t, const bf16* __restrict__ h2in)
{
    const int nv = g_nvalid[t];
    const int i0 = blockIdx.x * 2;
    if (i0 >= nv) return;
    const bool two = (i0 + 1 < nv);

    __shared__ float s_a2[2][512];
    __shared__ float s_wf[512];
    __shared__ float s_p[8][128];
    __shared__ float s_sc[2][128];
    __shared__ float s_al[2][128];

    const int tid = threadIdx.x;
    s_a2[0][tid] = g_att2gate[i0*1024 + tid];
    s_a2[1][tid] = two ? g_att2gate[(i0+1)*1024 + tid] : 0.f;
    s_wf[tid] = wfull[tid];
    __syncthreads();

    const int j = tid & 127, ks = tid >> 7;
    float p0 = 0.f, p1 = 0.f;
    const float* a1p = g_att1T + (size_t)(ks*128)*B_ + j;
    #pragma unroll 4
    for (int k = 0; k < 128; k++) {
        float a1 = a1p[(size_t)k*B_];
        float w  = s_wf[ks*128 + k];
        p0 = fmaf(fmaxf(a1 + s_a2[0][ks*128 + k], 0.f), w, p0);
        p1 = fmaf(fmaxf(a1 + s_a2[1][ks*128 + k], 0.f), w, p1);
    }
    s_p[ks*2][j] = p0;
    s_p[ks*2 + 1][j] = p1;
    __syncthreads();

    if (tid < 256) {
        int row = tid >> 7, jj = tid & 127;
        float sc = s_p[row][jj] + s_p[2+row][jj] + s_p[4+row][jj] + s_p[6+row][jj] + bfull[0];
        s_sc[row][jj] = (jj < nv) ? sc : -3.0e38f;
    }
    __syncthreads();

    if (tid < 64) {
        int row = tid >> 5, l = tid & 31;
        float vv[4], m = -3.0e38f;
        #pragma unroll
        for (int u = 0; u < 4; u++) { vv[u] = s_sc[row][l + 32*u]; m = fmaxf(m, vv[u]); }
        #pragma unroll
        for (int o = 16; o > 0; o >>= 1) m = fmaxf(m, __shfl_xor_sync(0xffffffffu, m, o));
        float sum = 0.f;
        #pragma unroll
        for (int u = 0; u < 4; u++) { vv[u] = expf(vv[u] - m); sum += vv[u]; }
        #pragma unroll
        for (int o = 16; o > 0; o >>= 1) sum += __shfl_xor_sync(0xffffffffu, sum, o);
        float inv = 1.f / sum;
        #pragma unroll
        for (int u = 0; u < 4; u++) s_al[row][l + 32*u] = vv[u] * inv;
    }
    __syncthreads();

    const int d = tid;
    float aw0 = 0.f, aw1 = 0.f;
    #pragma unroll 4
    for (int jj = 0; jj < 128; jj++) {
        float e = g_enc[jj*512 + d];
        aw0 = fmaf(s_al[0][jj], e, aw0);
        aw1 = fmaf(s_al[1][jj], e, aw1);
    }

    {
        int cap = caps[g_order[i0]*T_ + t];
        bf16* xr = g_xcat2 + (size_t)i0*4608;
        bf16 hi, lo;
        split2(emb[(size_t)cap*512 + d], hi, lo);
        xr[d] = hi; xr[1536 + d] = hi; xr[3072 + d] = lo;
        float gt = g_att2gate[i0*1024 + 512 + d];
        split2(gt * aw0, hi, lo);
        xr[512 + d] = hi; xr[1536 + 512 + d] = hi; xr[3072 + 512 + d] = lo;
        bf16 hh = h2in[i0*1536 + d], hl = h2in[i0*1536 + 1024 + d];
        xr[1024 + d] = hh; xr[1536 + 1024 + d] = hh; xr[3072 + 1024 + d] = hl;
    }
    if (two) {
        int i1 = i0 + 1;
        int cap = caps[g_order[i1]*T_ + t];
        bf16* xr = g_xcat2 + (size_t)i1*4608;
        bf16 hi, lo;
        split2(emb[(size_t)cap*512 + d], hi, lo);
        xr[d] = hi; xr[1536 + d] = hi; xr[3072 + d] = lo;
        float gt = g_att2gate[i1*1024 + 512 + d];
        split2(gt * aw1, hi, lo);
        xr[512 + d] = hi; xr[1536 + 512 + d] = hi; xr[3072 + 512 + d] = lo;
        bf16 hh = h2in[i1*1536 + d], hl = h2in[i1*1536 + 1024 + d];
        xr[1024 + d] = hh; xr[1536 + 1024 + d] = hh; xr[3072 + 1024 + d] = hl;
    }
}

// ---------------- host launch ----------------
extern "C" void kernel_launch(void* const* d_in, const int* in_sizes, int n_in,
                              void* d_out, int out_size) {
    const float* encoder_out = (const float*)d_in[0];
    const int*   caps        = (const int*)  d_in[1];
    const int*   capl        = (const int*)  d_in[2];
    const float* W_enc  = (const float*)d_in[3];
    const float* b_enc  = (const float*)d_in[4];
    const float* W_dec  = (const float*)d_in[5];
    const float* b_dec  = (const float*)d_in[6];
    const float* W_full = (const float*)d_in[7];
    const float* b_full = (const float*)d_in[8];
    const float* W_init_h = (const float*)d_in[9];
    const float* b_init_h = (const float*)d_in[10];
    const float* W_init_c = (const float*)d_in[11];
    const float* b_init_c = (const float*)d_in[12];
    const float* W_fbeta  = (const float*)d_in[13];
    const float* b_fbeta  = (const float*)d_in[14];
    const float* W_fc     = (const float*)d_in[15];
    const float* b_fc     = (const float*)d_in[16];
    const float* emb      = (const float*)d_in[17];
    const float* W_ih     = (const float*)d_in[18];
    const float* b_ih     = (const float*)d_in[19];
    const float* W_hh     = (const float*)d_in[20];
    const float* b_hh     = (const float*)d_in[21];
    float* out = (float*)d_out;

    float *p_enc, *p_att1, *p_h, *p_c, *p_a2g, *p_Wc1, *p_bc1, *p_Wbig, *p_bbig;
    bf16  *p_h2, *p_xcat2, *p_Wc1b, *p_Wbigb, *p_Wfcb;
    cudaGetSymbolAddress((void**)&p_enc,   g_enc);
    cudaGetSymbolAddress((void**)&p_att1,  g_att1);
    cudaGetSymbolAddress((void**)&p_h,     g_h);
    cudaGetSymbolAddress((void**)&p_c,     g_c);
    cudaGetSymbolAddress((void**)&p_a2g,   g_att2gate);
    cudaGetSymbolAddress((void**)&p_Wc1,   g_Wc1);
    cudaGetSymbolAddress((void**)&p_bc1,   g_bc1);
    cudaGetSymbolAddress((void**)&p_Wbig,  g_Wbig);
    cudaGetSymbolAddress((void**)&p_bbig,  g_bbig);
    cudaGetSymbolAddress((void**)&p_h2,    g_h2);
    cudaGetSymbolAddress((void**)&p_xcat2, g_xcat2);
    cudaGetSymbolAddress((void**)&p_Wc1b,  g_Wc1b);
    cudaGetSymbolAddress((void**)&p_Wbigb, g_Wbigb);
    cudaGetSymbolAddress((void**)&p_Wfcb,  g_Wfcb);

    static cudaStream_t s2 = nullptr;
    static cudaEvent_t evF[2], evJ[2];
    if (!s2) {
        cudaStreamCreateWithFlags(&s2, cudaStreamNonBlocking);
        for (int i = 0; i < 2; i++) {
            cudaEventCreateWithFlags(&evF[i], cudaEventDisableTiming);
            cudaEventCreateWithFlags(&evJ[i], cudaEventDisableTiming);
        }
    }

    // ---- prep ----
    k_prep<<<1, 128>>>(capl);
    k_gather<<<128, 128>>>(encoder_out);
    k_buildWc1<<<1024, 128>>>(W_dec, b_dec, W_fbeta, b_fbeta);
    k_buildWbig<<<2048, 128>>>(W_ih, b_ih, W_hh, b_hh);
    k_cvt3<512> <<<1024, 128>>>(p_Wc1,  p_Wc1b);
    k_cvt3<1536><<<2048, 128>>>(p_Wbig, p_Wbigb);
    k_cvt3<512> <<<4096, 128>>>(W_fc,   p_Wfcb);
    k_gemm32<<<dim3(16,4), 256>>>(p_enc, W_init_h, b_init_h, p_h,    512, 512);
    k_gemm32<<<dim3(16,4), 256>>>(p_enc, W_init_c, b_init_c, p_c,    512, 512);
    k_gemm32<<<dim3(16,4), 256>>>(p_enc, W_enc,    b_enc,    p_att1, 512, 512);
    k_transpose<<<dim3(16,4), dim3(32,8)>>>();
    k_split_h<<<128, 512>>>();

    // ---- time steps ----
    for (int t = 0; t < T_; t++) {
        const bf16* hin = p_h2 + (size_t)(t & 1) * HB_;
        bf16* hout = p_h2 + (size_t)((t + 1) & 1) * HB_;

        k_mma<1><<<dim3(16,4), 256>>>(hin, p_Wc1b, p_bc1, p_a2g, nullptr, 1536, t, 1024);
        k_attn<<<64, 512>>>(caps, emb, W_full, b_full, t, hin);
        if (t >= 2) cudaStreamWaitEvent(0, evJ[t & 1], 0);
        k_mma<2><<<dim3(32,4), 256>>>(p_xcat2, p_Wbigb, p_bbig, nullptr, hout, 4608, t, 0);
        cudaEventRecord(evF[t & 1], 0);
        cudaStreamWaitEvent(s2, evF[t & 1], 0);
        k_mma<3><<<dim3(64,4), 256, 0, s2>>>(hout, p_Wfcb, b_fc, out, nullptr, 1536, t, 0);
        cudaEventRecord(evJ[t & 1], s2);
    }
    cudaStreamWaitEvent(0, evJ[0], 0);
    cudaStreamWaitEvent(0, evJ[1], 0);
}